// round 5
// baseline (speedup 1.0000x reference)
#include <cuda_runtime.h>
#include <cuda_bf16.h>

#define ND 20000
#define NP 20000
#define NN 20000
#define FH 512
#define EE 320000

// ---------------- device scratch (static allocations only) ----------------
__device__ float g_Xd[ND * FH];
__device__ float g_Xp[NP * FH];
__device__ float g_Da[ND * FH];
__device__ float g_Pa[NP * FH];
__device__ float g_Mn[NN * FH];
__device__ float g_Wsum[FH * FH];
__device__ float g_bsum[FH];
__device__ float g_sum[FH];
__device__ float g_sq[FH];
__device__ float g_scale[FH];
__device__ float g_shift[FH];
__device__ int   g_off[4 * (NN + 1)];
__device__ int   g_cur[4 * (NN + 1)];
__device__ int   g_val[4 * EE];

// ---------------- CSR build ----------------
__global__ void hist_kernel(const int* __restrict__ grp, int* __restrict__ off, int E) {
    int e = blockIdx.x * blockDim.x + threadIdx.x;
    if (e < E) atomicAdd(&off[grp[e] + 1], 1);
}

// single-block inclusive scan over off[1..n] (off[0] stays 0)
__global__ void scan_kernel(int* __restrict__ off, int n) {
    __shared__ int ssum[1024];
    const int T = 1024;
    int t = threadIdx.x;
    int chunk = (n + T - 1) / T;
    int lo = 1 + t * chunk;
    int hi = lo + chunk;
    if (hi > n + 1) hi = n + 1;
    int s = 0;
    for (int i = lo; i < hi && i <= n; i++) s += off[i];
    ssum[t] = s;
    __syncthreads();
    for (int d = 1; d < T; d <<= 1) {
        int v = (t >= d) ? ssum[t - d] : 0;
        __syncthreads();
        ssum[t] += v;
        __syncthreads();
    }
    int run = (t > 0) ? ssum[t - 1] : 0;
    for (int i = lo; i < hi && i <= n; i++) {
        run += off[i];
        off[i] = run;
    }
}

__global__ void fill_kernel(const int* __restrict__ grp, const int* __restrict__ oth,
                            int* __restrict__ cur, int* __restrict__ val, int E) {
    int e = blockIdx.x * blockDim.x + threadIdx.x;
    if (e < E) {
        int p = atomicAdd(&cur[grp[e]], 1);
        val[p] = oth[e];
    }
}

// ---------------- segment mean via CSR gather ----------------
__global__ void seg_mean_kernel(const float* __restrict__ X, const int* __restrict__ off,
                                const int* __restrict__ val, float* __restrict__ out) {
    int d = blockIdx.x;
    int s = off[d], e = off[d + 1];
    int c = threadIdx.x * 4;  // 128 threads * 4 = 512
    float4 acc = make_float4(0.f, 0.f, 0.f, 0.f);
    for (int j = s; j < e; j++) {
        int nb = __ldg(&val[j]);
        float4 v = *(const float4*)(X + (size_t)nb * FH + c);
        acc.x += v.x; acc.y += v.y; acc.z += v.z; acc.w += v.w;
    }
    int deg = e - s;
    float inv = 1.0f / (float)(deg > 0 ? deg : 1);
    acc.x *= inv; acc.y *= inv; acc.z *= inv; acc.w *= inv;
    *(float4*)(out + (size_t)d * FH + c) = acc;
}

// ---------------- weight fold (Ws0+Ws2+Ws3, b0+b2+b3) ----------------
__global__ void wsum_kernel(const float* __restrict__ Ws, const float* __restrict__ b,
                            float* __restrict__ Wsum, float* __restrict__ bsum) {
    int i = blockIdx.x * blockDim.x + threadIdx.x;
    if (i < FH * FH)
        Wsum[i] = Ws[i] + Ws[2 * FH * FH + i] + Ws[3 * FH * FH + i];
    if (i < FH)
        bsum[i] = b[i] + b[2 * FH + i] + b[3 * FH + i];
}

// ---------------- GEMM: C[M,512] (+)= A[M,512] @ B[512,512] (+bias) ----------------
// 128x128 tile, BK=8, 256 threads, 8x8 per thread with 4+64 split fragments.
__global__ void __launch_bounds__(256) gemm512_kernel(
    const float* __restrict__ A, const float* __restrict__ B, float* __restrict__ C,
    int M, const float* __restrict__ bias, int accumulate) {
    const int K = 512, N = 512;
    __shared__ float As[8][128];
    __shared__ float Bs[8][128];
    int tid = threadIdx.x;
    int row0 = blockIdx.x * 128;
    int col0 = blockIdx.y * 128;
    int tx = tid & 15;
    int ty = tid >> 4;

    float acc[8][8];
#pragma unroll
    for (int i = 0; i < 8; i++)
#pragma unroll
        for (int j = 0; j < 8; j++) acc[i][j] = 0.f;

    int arow = tid >> 1;
    int acol = (tid & 1) * 4;
    int brow = tid >> 5;
    int bcol = (tid & 31) * 4;

    for (int k0 = 0; k0 < K; k0 += 8) {
        float4 av;
        if (row0 + arow < M)
            av = *(const float4*)(A + (size_t)(row0 + arow) * K + k0 + acol);
        else
            av = make_float4(0.f, 0.f, 0.f, 0.f);
        As[acol + 0][arow] = av.x;
        As[acol + 1][arow] = av.y;
        As[acol + 2][arow] = av.z;
        As[acol + 3][arow] = av.w;
        float4 bv = *(const float4*)(B + (size_t)(k0 + brow) * N + col0 + bcol);
        *(float4*)&Bs[brow][bcol] = bv;
        __syncthreads();
#pragma unroll
        for (int kk = 0; kk < 8; kk++) {
            float a[8], b[8];
            float4 aA = *(const float4*)&As[kk][ty * 4];
            float4 aB = *(const float4*)&As[kk][ty * 4 + 64];
            a[0] = aA.x; a[1] = aA.y; a[2] = aA.z; a[3] = aA.w;
            a[4] = aB.x; a[5] = aB.y; a[6] = aB.z; a[7] = aB.w;
            float4 bA = *(const float4*)&Bs[kk][tx * 4];
            float4 bB = *(const float4*)&Bs[kk][tx * 4 + 64];
            b[0] = bA.x; b[1] = bA.y; b[2] = bA.z; b[3] = bA.w;
            b[4] = bB.x; b[5] = bB.y; b[6] = bB.z; b[7] = bB.w;
#pragma unroll
            for (int i = 0; i < 8; i++)
#pragma unroll
                for (int j = 0; j < 8; j++) acc[i][j] = fmaf(a[i], b[j], acc[i][j]);
        }
        __syncthreads();
    }

    // epilogue
#pragma unroll
    for (int ii = 0; ii < 2; ii++) {
#pragma unroll
        for (int ir = 0; ir < 4; ir++) {
            int r = row0 + ty * 4 + ii * 64 + ir;
            if (r >= M) continue;
            int i = ii * 4 + ir;
#pragma unroll
            for (int jj = 0; jj < 2; jj++) {
                int c = col0 + tx * 4 + jj * 64;
                int j = jj * 4;
                float4 v = make_float4(acc[i][j], acc[i][j + 1], acc[i][j + 2], acc[i][j + 3]);
                if (bias) {
                    float4 bi = *(const float4*)(bias + c);
                    v.x += bi.x; v.y += bi.y; v.z += bi.z; v.w += bi.w;
                }
                float* cp = C + (size_t)r * N + c;
                if (accumulate) {
                    float4 o = *(const float4*)cp;
                    v.x += o.x; v.y += o.y; v.z += o.z; v.w += o.w;
                }
                *(float4*)cp = v;
            }
        }
    }
}

// ---------------- BN ----------------
__global__ void colstats_kernel(const float* __restrict__ X, int M,
                                float* __restrict__ sum, float* __restrict__ sq) {
    int c = threadIdx.x;  // 512
    float s = 0.f, s2 = 0.f;
    for (int r = blockIdx.x; r < M; r += gridDim.x) {
        float v = X[(size_t)r * FH + c];
        s += v;
        s2 += v * v;
    }
    atomicAdd(&sum[c], s);
    atomicAdd(&sq[c], s2);
}

__global__ void bn_finalize_kernel(const float* __restrict__ sum, const float* __restrict__ sq,
                                   const float* __restrict__ gamma, const float* __restrict__ beta,
                                   int M, float* __restrict__ scale, float* __restrict__ shift) {
    int c = threadIdx.x;
    float m = sum[c] / (float)M;
    float var = sq[c] / (float)M - m * m;
    float rstd = rsqrtf(var + 1e-5f);
    float sc = gamma[c] * rstd;
    scale[c] = sc;
    shift[c] = beta[c] - m * sc;
}

__global__ void bnrelu_kernel(const float* __restrict__ X, float* __restrict__ Y, int M,
                              const float* __restrict__ scale, const float* __restrict__ shift) {
    int i = blockIdx.x * blockDim.x + threadIdx.x;
    int total = M * FH / 4;
    if (i >= total) return;
    int c = (i & 127) * 4;
    float4 x = ((const float4*)X)[i];
    float4 sc = *(const float4*)(scale + c);
    float4 sh = *(const float4*)(shift + c);
    float4 y;
    y.x = fmaxf(fmaf(x.x, sc.x, sh.x), 0.f);
    y.y = fmaxf(fmaf(x.y, sc.y, sh.y), 0.f);
    y.z = fmaxf(fmaf(x.z, sc.z, sh.z), 0.f);
    y.w = fmaxf(fmaf(x.w, sc.w, sh.w), 0.f);
    ((float4*)Y)[i] = y;
}

// ---------------- host orchestration ----------------
static inline void launch_gemm(const float* A, const float* B, float* C, int M,
                               const float* bias, int acc) {
    dim3 grid((M + 127) / 128, FH / 128);
    gemm512_kernel<<<grid, 256>>>(A, B, C, M, bias, acc);
}

extern "C" void kernel_launch(void* const* d_in, const int* in_sizes, int n_in,
                              void* d_out, int out_size) {
    const float* h_d  = (const float*)d_in[0];
    const float* h_p  = (const float*)d_in[1];
    const float* Ws1  = (const float*)d_in[2];
    const float* Wn1  = (const float*)d_in[3];
    const float* b1   = (const float*)d_in[4];
    const float* Ws2  = (const float*)d_in[5];
    const float* Wn2  = (const float*)d_in[6];
    const float* b2   = (const float*)d_in[7];
    const float* bng  = (const float*)d_in[8];
    const float* bnb  = (const float*)d_in[9];
    const float* pWd  = (const float*)d_in[10];
    const float* pbd  = (const float*)d_in[11];
    const float* pWp  = (const float*)d_in[12];
    const float* pbp  = (const float*)d_in[13];
    const int* a_src  = (const int*)d_in[14];
    const int* a_dst  = (const int*)d_in[15];
    const int* i_src  = (const int*)d_in[16];
    const int* i_dst  = (const int*)d_in[17];
    float* out = (float*)d_out;

    float *Xd, *Xp, *Da, *Pa, *Mn, *Wsum, *bsum, *sum, *sq, *scale, *shift;
    int *off, *cur, *val;
    cudaGetSymbolAddress((void**)&Xd, g_Xd);
    cudaGetSymbolAddress((void**)&Xp, g_Xp);
    cudaGetSymbolAddress((void**)&Da, g_Da);
    cudaGetSymbolAddress((void**)&Pa, g_Pa);
    cudaGetSymbolAddress((void**)&Mn, g_Mn);
    cudaGetSymbolAddress((void**)&Wsum, g_Wsum);
    cudaGetSymbolAddress((void**)&bsum, g_bsum);
    cudaGetSymbolAddress((void**)&sum, g_sum);
    cudaGetSymbolAddress((void**)&sq, g_sq);
    cudaGetSymbolAddress((void**)&scale, g_scale);
    cudaGetSymbolAddress((void**)&shift, g_shift);
    cudaGetSymbolAddress((void**)&off, g_off);
    cudaGetSymbolAddress((void**)&cur, g_cur);
    cudaGetSymbolAddress((void**)&val, g_val);

    // Build 4 CSRs: 0:(grp=a_dst, oth=a_src)  1:(a_src, a_dst)
    //               2:(i_dst, i_src)          3:(i_src, i_dst)
    const int* grps[4] = {a_dst, a_src, i_dst, i_src};
    const int* oths[4] = {a_src, a_dst, i_src, i_dst};
    for (int r = 0; r < 4; r++) {
        int* offr = off + r * (NN + 1);
        int* curr = cur + r * (NN + 1);
        int* valr = val + r * EE;
        cudaMemsetAsync(offr, 0, (NN + 1) * sizeof(int), 0);
        hist_kernel<<<(EE + 255) / 256, 256>>>(grps[r], offr, EE);
        scan_kernel<<<1, 1024>>>(offr, NN);
        cudaMemcpyAsync(curr, offr, (NN + 1) * sizeof(int), cudaMemcpyDeviceToDevice, 0);
        fill_kernel<<<(EE + 255) / 256, 256>>>(grps[r], oths[r], curr, valr, EE);
    }

    const float* inD = h_d;
    const float* inP = h_p;

    for (int li = 0; li < 2; li++) {
        const float* Ws = li ? Ws2 : Ws1;
        const float* Wn = li ? Wn2 : Wn1;
        const float* bb = li ? b2 : b1;

        wsum_kernel<<<(FH * FH + 255) / 256, 256>>>(Ws, bb, Wsum, bsum);

        // ---- disease: d1 = Xd @ Ws[1] + segmean(Xp, by a_src) @ Wn[1] + b[1]
        launch_gemm(inD, Ws + 1 * FH * FH, Da, ND, bb + FH, 0);
        seg_mean_kernel<<<NN, 128>>>(inP, off + 1 * (NN + 1), val + 1 * EE, Mn);
        launch_gemm(Mn, Wn + 1 * FH * FH, Da, ND, nullptr, 1);

        // ---- protein: p = Xp @ (Ws0+Ws2+Ws3) + (b0+b2+b3) + sum of 3 neigh terms
        launch_gemm(inP, Wsum, Pa, NP, bsum, 0);
        seg_mean_kernel<<<NN, 128>>>(inD, off + 0 * (NN + 1), val + 0 * EE, Mn);
        launch_gemm(Mn, Wn + 0 * FH * FH, Pa, NP, nullptr, 1);
        seg_mean_kernel<<<NN, 128>>>(inP, off + 2 * (NN + 1), val + 2 * EE, Mn);
        launch_gemm(Mn, Wn + 2 * FH * FH, Pa, NP, nullptr, 1);
        seg_mean_kernel<<<NN, 128>>>(inP, off + 3 * (NN + 1), val + 3 * EE, Mn);
        launch_gemm(Mn, Wn + 3 * FH * FH, Pa, NP, nullptr, 1);

        // ---- BN + ReLU (disease)
        cudaMemsetAsync(sum, 0, FH * sizeof(float), 0);
        cudaMemsetAsync(sq, 0, FH * sizeof(float), 0);
        colstats_kernel<<<160, FH>>>(Da, ND, sum, sq);
        bn_finalize_kernel<<<1, FH>>>(sum, sq, bng + (li * 2 + 0) * FH, bnb + (li * 2 + 0) * FH,
                                      ND, scale, shift);
        bnrelu_kernel<<<(ND * FH / 4 + 255) / 256, 256>>>(Da, Xd, ND, scale, shift);

        // ---- BN + ReLU (protein)
        cudaMemsetAsync(sum, 0, FH * sizeof(float), 0);
        cudaMemsetAsync(sq, 0, FH * sizeof(float), 0);
        colstats_kernel<<<160, FH>>>(Pa, NP, sum, sq);
        bn_finalize_kernel<<<1, FH>>>(sum, sq, bng + (li * 2 + 1) * FH, bnb + (li * 2 + 1) * FH,
                                      NP, scale, shift);
        bnrelu_kernel<<<(NP * FH / 4 + 255) / 256, 256>>>(Pa, Xp, NP, scale, shift);

        inD = Xd;
        inP = Xp;
    }

    // final projections straight into d_out: [out_d ; out_p]
    launch_gemm(inD, pWd, out, ND, pbd, 0);
    launch_gemm(inP, pWp, out + (size_t)ND * FH, NP, pbp, 0);
}

// round 9
// speedup vs baseline: 1.9961x; 1.9961x over previous
#include <cuda_runtime.h>
#include <cuda_bf16.h>
#include <cstdint>

#define ND 20000
#define NP 20000
#define NN 20000
#define FH 512
#define FF (FH * FH)
#define EE 320000

// ---------------- device scratch (static, no allocation) ----------------
__device__ float g_Xd[ND * FH], g_Xp[NP * FH], g_Da[ND * FH], g_Pa[NP * FH];
__device__ __align__(16) __nv_bfloat16 g_Xdh[ND * FH], g_Xdl[ND * FH];
__device__ __align__(16) __nv_bfloat16 g_Xph[NP * FH], g_Xpl[NP * FH];
__device__ __align__(16) __nv_bfloat16 g_Mh[4][NN * FH], g_Ml[4][NN * FH];
__device__ __align__(16) __nv_bfloat16 g_Wth[6][FF], g_Wtl[6][FF];
__device__ float g_Wsum[FF], g_bsum[FH], g_sum[FH], g_sq[FH], g_scale[FH], g_shift[FH];
__device__ int g_off[4 * (NN + 1)], g_cur[4 * (NN + 1)], g_val[4 * EE];

// ---------------- helpers ----------------
__device__ __forceinline__ uint32_t smem_u32(const void* p) {
    uint32_t a;
    asm("{ .reg .u64 t; cvta.to.shared.u64 t, %1; cvt.u32.u64 %0, t; }" : "=r"(a) : "l"(p));
    return a;
}

#define LDSM4(r, addr) \
    asm volatile("ldmatrix.sync.aligned.m8n8.x4.shared.b16 {%0,%1,%2,%3}, [%4];" \
                 : "=r"((r)[0]), "=r"((r)[1]), "=r"((r)[2]), "=r"((r)[3]) : "r"(addr))

#define MMA16816(c, a, b0, b1) \
    asm volatile("mma.sync.aligned.m16n8k16.row.col.f32.bf16.bf16.f32 " \
                 "{%0,%1,%2,%3}, {%4,%5,%6,%7}, {%8,%9}, {%0,%1,%2,%3};" \
                 : "+f"((c)[0]), "+f"((c)[1]), "+f"((c)[2]), "+f"((c)[3]) \
                 : "r"((a)[0]), "r"((a)[1]), "r"((a)[2]), "r"((a)[3]), "r"(b0), "r"(b1))

#define CP_ASYNC16(dst, src, sz) \
    asm volatile("cp.async.cg.shared.global [%0], [%1], 16, %2;" :: "r"(dst), "l"(src), "r"(sz) : "memory")
#define CP_COMMIT() asm volatile("cp.async.commit_group;" ::: "memory")
#define CP_WAIT1() asm volatile("cp.async.wait_group 1;" ::: "memory")

// ---------------- CSR build ----------------
__global__ void hist_kernel(const int* __restrict__ grp, int* __restrict__ off, int E) {
    int e = blockIdx.x * blockDim.x + threadIdx.x;
    if (e < E) atomicAdd(&off[grp[e] + 1], 1);
}
__global__ void scan_kernel(int* __restrict__ off, int n) {
    __shared__ int ssum[1024];
    const int T = 1024;
    int t = threadIdx.x;
    int chunk = (n + T - 1) / T;
    int lo = 1 + t * chunk;
    int hi = lo + chunk;
    if (hi > n + 1) hi = n + 1;
    int s = 0;
    for (int i = lo; i < hi && i <= n; i++) s += off[i];
    ssum[t] = s;
    __syncthreads();
    for (int d = 1; d < T; d <<= 1) {
        int v = (t >= d) ? ssum[t - d] : 0;
        __syncthreads();
        ssum[t] += v;
        __syncthreads();
    }
    int run = (t > 0) ? ssum[t - 1] : 0;
    for (int i = lo; i < hi && i <= n; i++) {
        run += off[i];
        off[i] = run;
    }
}
__global__ void fill_kernel(const int* __restrict__ grp, const int* __restrict__ oth,
                            int* __restrict__ cur, int* __restrict__ val, int E) {
    int e = blockIdx.x * blockDim.x + threadIdx.x;
    if (e < E) {
        int p = atomicAdd(&cur[grp[e]], 1);
        val[p] = oth[e];
    }
}

// ---------------- segment mean -> bf16 hi/lo ----------------
__global__ void seg_mean_split(const float* __restrict__ X, const int* __restrict__ off,
                               const int* __restrict__ val, __nv_bfloat16* __restrict__ H,
                               __nv_bfloat16* __restrict__ L) {
    int d = blockIdx.x;
    int s = off[d], e = off[d + 1];
    int c = threadIdx.x * 4;
    float4 acc = make_float4(0.f, 0.f, 0.f, 0.f);
    for (int j = s; j < e; j++) {
        int nb = __ldg(&val[j]);
        float4 v = *(const float4*)(X + (size_t)nb * FH + c);
        acc.x += v.x; acc.y += v.y; acc.z += v.z; acc.w += v.w;
    }
    int deg = e - s;
    float inv = 1.0f / (float)(deg > 0 ? deg : 1);
    float v0 = acc.x * inv, v1 = acc.y * inv, v2 = acc.z * inv, v3 = acc.w * inv;
    __nv_bfloat16 h0 = __float2bfloat16(v0), h1 = __float2bfloat16(v1);
    __nv_bfloat16 h2 = __float2bfloat16(v2), h3 = __float2bfloat16(v3);
    __nv_bfloat16 l0 = __float2bfloat16(v0 - __bfloat162float(h0));
    __nv_bfloat16 l1 = __float2bfloat16(v1 - __bfloat162float(h1));
    __nv_bfloat16 l2 = __float2bfloat16(v2 - __bfloat162float(h2));
    __nv_bfloat16 l3 = __float2bfloat16(v3 - __bfloat162float(h3));
    __nv_bfloat162* Hp = (__nv_bfloat162*)(H + (size_t)d * FH + c);
    __nv_bfloat162* Lp = (__nv_bfloat162*)(L + (size_t)d * FH + c);
    Hp[0] = __halves2bfloat162(h0, h1);
    Hp[1] = __halves2bfloat162(h2, h3);
    Lp[0] = __halves2bfloat162(l0, l1);
    Lp[1] = __halves2bfloat162(l2, l3);
}

// ---------------- fp32 -> bf16 hi/lo split ----------------
__global__ void cvt_split(const float* __restrict__ X, __nv_bfloat16* __restrict__ H,
                          __nv_bfloat16* __restrict__ L, int n4) {
    int i = blockIdx.x * blockDim.x + threadIdx.x;
    if (i >= n4) return;
    float4 x = ((const float4*)X)[i];
    __nv_bfloat16 h0 = __float2bfloat16(x.x), h1 = __float2bfloat16(x.y);
    __nv_bfloat16 h2 = __float2bfloat16(x.z), h3 = __float2bfloat16(x.w);
    __nv_bfloat16 l0 = __float2bfloat16(x.x - __bfloat162float(h0));
    __nv_bfloat16 l1 = __float2bfloat16(x.y - __bfloat162float(h1));
    __nv_bfloat16 l2 = __float2bfloat16(x.z - __bfloat162float(h2));
    __nv_bfloat16 l3 = __float2bfloat16(x.w - __bfloat162float(h3));
    __nv_bfloat162* Hp = (__nv_bfloat162*)(H + (size_t)i * 4);
    __nv_bfloat162* Lp = (__nv_bfloat162*)(L + (size_t)i * 4);
    Hp[0] = __halves2bfloat162(h0, h1);
    Hp[1] = __halves2bfloat162(h2, h3);
    Lp[0] = __halves2bfloat162(l0, l1);
    Lp[1] = __halves2bfloat162(l2, l3);
}

// ---------------- weight transpose + split: W[K,N] -> T[N,K] hi/lo ----------------
__global__ void wtrans_split(const float* __restrict__ W, __nv_bfloat16* __restrict__ Th,
                             __nv_bfloat16* __restrict__ Tl) {
    __shared__ float t[32][33];
    int k = blockIdx.y * 32 + threadIdx.y;
    int n = blockIdx.x * 32 + threadIdx.x;
    t[threadIdx.y][threadIdx.x] = W[(size_t)k * FH + n];
    __syncthreads();
    int nn = blockIdx.x * 32 + threadIdx.y;
    int kk = blockIdx.y * 32 + threadIdx.x;
    float v = t[threadIdx.x][threadIdx.y];
    __nv_bfloat16 h = __float2bfloat16(v);
    __nv_bfloat16 l = __float2bfloat16(v - __bfloat162float(h));
    Th[(size_t)nn * FH + kk] = h;
    Tl[(size_t)nn * FH + kk] = l;
}

// ---------------- weight fold ----------------
__global__ void wsum_kernel(const float* __restrict__ Ws, const float* __restrict__ b,
                            float* __restrict__ Wsum, float* __restrict__ bsum) {
    int i = blockIdx.x * blockDim.x + threadIdx.x;
    if (i < FF) Wsum[i] = Ws[i] + Ws[2 * FF + i] + Ws[3 * FF + i];
    if (i < FH) bsum[i] = b[i] + b[2 * FH + i] + b[3 * FH + i];
}

// ---------------- mma.sync bf16 multi-part GEMM ----------------
// C[M,512] = sum_parts A_p[M,512](bf16) @ B_p[512,512]^T(bf16, stored [N][K]) + bias
// CTA tile 128x128, BK=32, 8 warps (2x4), warp tile 64x32, 3-stage cp.async.
struct GemmArgs {
    const __nv_bfloat16* A[12];
    const __nv_bfloat16* B[12];
    int P;   // number of (A,B) parts; effective K = P*512
    int M;
    const float* bias;
    float* C;
};

#define BM 128
#define BN 128
#define BKk 32
#define STAGES 3
#define STAGE_SZ 16384  // A 8KB + B 8KB

__device__ __forceinline__ void gemm_prefetch(const GemmArgs& args, int kt, uint32_t sbase,
                                              int tid, int row0, int col0) {
    int part = kt >> 4, kk = kt & 15;
    int stage = kt % STAGES;
    const __nv_bfloat16* aP = args.A[part];
    const __nv_bfloat16* bP = args.B[part];
    int k0 = kk * BKk;
    uint32_t sA = sbase + stage * STAGE_SZ;
    uint32_t sB = sA + 8192;
#pragma unroll
    for (int i = 0; i < 2; i++) {
        int idx = tid + i * 256;
        int r = idx >> 2, ch = idx & 3;
        const __nv_bfloat16* g = aP + (size_t)(row0 + r) * FH + k0 + ch * 8;
        uint32_t d = sA + r * 64 + ((ch ^ ((r >> 1) & 3)) << 4);
        int sz = (row0 + r < args.M) ? 16 : 0;
        CP_ASYNC16(d, g, sz);
    }
#pragma unroll
    for (int i = 0; i < 2; i++) {
        int idx = tid + i * 256;
        int r = idx >> 2, ch = idx & 3;
        const __nv_bfloat16* g = bP + (size_t)(col0 + r) * FH + k0 + ch * 8;
        uint32_t d = sB + r * 64 + ((ch ^ ((r >> 1) & 3)) << 4);
        CP_ASYNC16(d, g, 16);
    }
    CP_COMMIT();
}

__global__ void __launch_bounds__(256) gemm_mma_kernel(GemmArgs args) {
    __shared__ __align__(128) char smem[STAGES * STAGE_SZ];
    uint32_t sbase = smem_u32(smem);
    int tid = threadIdx.x;
    int w = tid >> 5, lane = tid & 31;
    int wm = w >> 2, wn = w & 3;
    int row0 = blockIdx.x * BM, col0 = blockIdx.y * BN;

    float c[4][4][4];
#pragma unroll
    for (int mi = 0; mi < 4; mi++)
#pragma unroll
        for (int ni = 0; ni < 4; ni++)
#pragma unroll
            for (int q = 0; q < 4; q++) c[mi][ni][q] = 0.f;

    const int T = args.P * 16;
    gemm_prefetch(args, 0, sbase, tid, row0, col0);
    gemm_prefetch(args, 1, sbase, tid, row0, col0);

    for (int kt = 0; kt < T; kt++) {
        CP_WAIT1();
        __syncthreads();
        if (kt + 2 < T)
            gemm_prefetch(args, kt + 2, sbase, tid, row0, col0);
        else
            CP_COMMIT();

        int stage = kt % STAGES;
        uint32_t sA = sbase + stage * STAGE_SZ;
        uint32_t sB = sA + 8192;
#pragma unroll
        for (int ks = 0; ks < 2; ks++) {
            int kc0 = ks * 2;
            uint32_t a[4][4];
#pragma unroll
            for (int mi = 0; mi < 4; mi++) {
                int r = wm * 64 + mi * 16 + (lane & 15);
                int ch = kc0 + (lane >> 4);
                uint32_t addr = sA + r * 64 + ((ch ^ ((r >> 1) & 3)) << 4);
                LDSM4(a[mi], addr);
            }
            uint32_t b[2][4];
#pragma unroll
            for (int nb = 0; nb < 2; nb++) {
                int r = wn * 32 + nb * 16 + ((lane >> 3) & 1) * 8 + (lane & 7);
                int ch = kc0 + (lane >> 4);
                uint32_t addr = sB + r * 64 + ((ch ^ ((r >> 1) & 3)) << 4);
                LDSM4(b[nb], addr);
            }
#pragma unroll
            for (int mi = 0; mi < 4; mi++)
#pragma unroll
                for (int ni = 0; ni < 4; ni++) {
                    uint32_t b0 = b[ni >> 1][ni & 1];
                    uint32_t b1 = b[ni >> 1][2 + (ni & 1)];
                    MMA16816(c[mi][ni], a[mi], b0, b1);
                }
        }
    }

    // epilogue: bias + store
    int gr = lane >> 2, gc = (lane & 3) * 2;
#pragma unroll
    for (int mi = 0; mi < 4; mi++) {
        int r0 = row0 + wm * 64 + mi * 16 + gr;
#pragma unroll
        for (int ni = 0; ni < 4; ni++) {
            int cc = col0 + wn * 32 + ni * 8 + gc;
            float2 bv = *(const float2*)(args.bias + cc);
            if (r0 < args.M) {
                float2 v = make_float2(c[mi][ni][0] + bv.x, c[mi][ni][1] + bv.y);
                *(float2*)(args.C + (size_t)r0 * FH + cc) = v;
            }
            if (r0 + 8 < args.M) {
                float2 v = make_float2(c[mi][ni][2] + bv.x, c[mi][ni][3] + bv.y);
                *(float2*)(args.C + (size_t)(r0 + 8) * FH + cc) = v;
            }
        }
    }
}

// ---------------- BN ----------------
__global__ void colstats_kernel(const float* __restrict__ X, int M,
                                float* __restrict__ sum, float* __restrict__ sq) {
    int c = threadIdx.x;
    float s = 0.f, s2 = 0.f;
    for (int r = blockIdx.x; r < M; r += gridDim.x) {
        float v = X[(size_t)r * FH + c];
        s += v;
        s2 += v * v;
    }
    atomicAdd(&sum[c], s);
    atomicAdd(&sq[c], s2);
}
__global__ void bn_finalize_kernel(const float* __restrict__ sum, const float* __restrict__ sq,
                                   const float* __restrict__ gamma, const float* __restrict__ beta,
                                   int M, float* __restrict__ scale, float* __restrict__ shift) {
    int c = threadIdx.x;
    float m = sum[c] / (float)M;
    float var = sq[c] / (float)M - m * m;
    float rstd = rsqrtf(var + 1e-5f);
    float sc = gamma[c] * rstd;
    scale[c] = sc;
    shift[c] = beta[c] - m * sc;
}
__global__ void bnrelu_split(const float* __restrict__ Xin, float* __restrict__ Y,
                             __nv_bfloat16* __restrict__ H, __nv_bfloat16* __restrict__ L,
                             int M, const float* __restrict__ scale,
                             const float* __restrict__ shift) {
    int i = blockIdx.x * blockDim.x + threadIdx.x;
    int total = M * FH / 4;
    if (i >= total) return;
    int c = (i & 127) * 4;
    float4 x = ((const float4*)Xin)[i];
    float4 sc = *(const float4*)(scale + c);
    float4 sh = *(const float4*)(shift + c);
    float4 y;
    y.x = fmaxf(fmaf(x.x, sc.x, sh.x), 0.f);
    y.y = fmaxf(fmaf(x.y, sc.y, sh.y), 0.f);
    y.z = fmaxf(fmaf(x.z, sc.z, sh.z), 0.f);
    y.w = fmaxf(fmaf(x.w, sc.w, sh.w), 0.f);
    ((float4*)Y)[i] = y;
    __nv_bfloat16 h0 = __float2bfloat16(y.x), h1 = __float2bfloat16(y.y);
    __nv_bfloat16 h2 = __float2bfloat16(y.z), h3 = __float2bfloat16(y.w);
    __nv_bfloat16 l0 = __float2bfloat16(y.x - __bfloat162float(h0));
    __nv_bfloat16 l1 = __float2bfloat16(y.y - __bfloat162float(h1));
    __nv_bfloat16 l2 = __float2bfloat16(y.z - __bfloat162float(h2));
    __nv_bfloat16 l3 = __float2bfloat16(y.w - __bfloat162float(h3));
    __nv_bfloat162* Hp = (__nv_bfloat162*)(H + (size_t)i * 4);
    __nv_bfloat162* Lp = (__nv_bfloat162*)(L + (size_t)i * 4);
    Hp[0] = __halves2bfloat162(h0, h1);
    Hp[1] = __halves2bfloat162(h2, h3);
    Lp[0] = __halves2bfloat162(l0, l1);
    Lp[1] = __halves2bfloat162(l2, l3);
}

// ---------------- host orchestration ----------------
static inline void add_term(GemmArgs& a, const __nv_bfloat16* Ah, const __nv_bfloat16* Al,
                            const __nv_bfloat16* Bh, const __nv_bfloat16* Bl) {
    a.A[a.P] = Ah; a.B[a.P] = Bh; a.P++;   // hi*hi
    a.A[a.P] = Al; a.B[a.P] = Bh; a.P++;   // lo*hi
    a.A[a.P] = Ah; a.B[a.P] = Bl; a.P++;   // hi*lo
}

extern "C" void kernel_launch(void* const* d_in, const int* in_sizes, int n_in,
                              void* d_out, int out_size) {
    const float* h_d = (const float*)d_in[0];
    const float* h_p = (const float*)d_in[1];
    const float* Ws1 = (const float*)d_in[2];
    const float* Wn1 = (const float*)d_in[3];
    const float* b1  = (const float*)d_in[4];
    const float* Ws2 = (const float*)d_in[5];
    const float* Wn2 = (const float*)d_in[6];
    const float* b2  = (const float*)d_in[7];
    const float* bng = (const float*)d_in[8];
    const float* bnb = (const float*)d_in[9];
    const float* pWd = (const float*)d_in[10];
    const float* pbd = (const float*)d_in[11];
    const float* pWp = (const float*)d_in[12];
    const float* pbp = (const float*)d_in[13];
    const int* a_src = (const int*)d_in[14];
    const int* a_dst = (const int*)d_in[15];
    const int* i_src = (const int*)d_in[16];
    const int* i_dst = (const int*)d_in[17];
    float* out = (float*)d_out;

    float *Xd, *Xp, *Da, *Pa, *Wsum, *bsum, *sum, *sq, *scale, *shift;
    __nv_bfloat16 *Xdh, *Xdl, *Xph, *Xpl, *MhB, *MlB, *WthB, *WtlB;
    int *off, *cur, *val;
    cudaGetSymbolAddress((void**)&Xd, g_Xd);
    cudaGetSymbolAddress((void**)&Xp, g_Xp);
    cudaGetSymbolAddress((void**)&Da, g_Da);
    cudaGetSymbolAddress((void**)&Pa, g_Pa);
    cudaGetSymbolAddress((void**)&Wsum, g_Wsum);
    cudaGetSymbolAddress((void**)&bsum, g_bsum);
    cudaGetSymbolAddress((void**)&sum, g_sum);
    cudaGetSymbolAddress((void**)&sq, g_sq);
    cudaGetSymbolAddress((void**)&scale, g_scale);
    cudaGetSymbolAddress((void**)&shift, g_shift);
    cudaGetSymbolAddress((void**)&Xdh, g_Xdh);
    cudaGetSymbolAddress((void**)&Xdl, g_Xdl);
    cudaGetSymbolAddress((void**)&Xph, g_Xph);
    cudaGetSymbolAddress((void**)&Xpl, g_Xpl);
    cudaGetSymbolAddress((void**)&MhB, g_Mh);
    cudaGetSymbolAddress((void**)&MlB, g_Ml);
    cudaGetSymbolAddress((void**)&WthB, g_Wth);
    cudaGetSymbolAddress((void**)&WtlB, g_Wtl);
    cudaGetSymbolAddress((void**)&off, g_off);
    cudaGetSymbolAddress((void**)&cur, g_cur);
    cudaGetSymbolAddress((void**)&val, g_val);

    __nv_bfloat16 *Mh[4], *Ml[4], *Wth[6], *Wtl[6];
    for (int i = 0; i < 4; i++) { Mh[i] = MhB + (size_t)i * NN * FH; Ml[i] = MlB + (size_t)i * NN * FH; }
    for (int i = 0; i < 6; i++) { Wth[i] = WthB + (size_t)i * FF; Wtl[i] = WtlB + (size_t)i * FF; }

    // ---- CSR build: 0:(a_dst<-a_src) 1:(a_src<-a_dst) 2:(i_dst<-i_src) 3:(i_src<-i_dst)
    const int* grps[4] = {a_dst, a_src, i_dst, i_src};
    const int* oths[4] = {a_src, a_dst, i_src, i_dst};
    for (int r = 0; r < 4; r++) {
        int* offr = off + r * (NN + 1);
        int* curr = cur + r * (NN + 1);
        int* valr = val + r * EE;
        cudaMemsetAsync(offr, 0, (NN + 1) * sizeof(int), 0);
        hist_kernel<<<(EE + 255) / 256, 256>>>(grps[r], offr, EE);
        scan_kernel<<<1, 1024>>>(offr, NN);
        cudaMemcpyAsync(curr, offr, (NN + 1) * sizeof(int), cudaMemcpyDeviceToDevice, 0);
        fill_kernel<<<(EE + 255) / 256, 256>>>(grps[r], oths[r], curr, valr, EE);
    }

    // ---- initial activation splits
    cvt_split<<<(ND * FH / 4 + 255) / 256, 256>>>(h_d, Xdh, Xdl, ND * FH / 4);
    cvt_split<<<(NP * FH / 4 + 255) / 256, 256>>>(h_p, Xph, Xpl, NP * FH / 4);

    const float* gInD = h_d;
    const float* gInP = h_p;
    dim3 wgrid(16, 16), wblock(32, 32);
    dim3 ggrid((ND + BM - 1) / BM, FH / BN);

    for (int li = 0; li < 2; li++) {
        const float* Ws = li ? Ws2 : Ws1;
        const float* Wn = li ? Wn2 : Wn1;
        const float* bb = li ? b2 : b1;

        wsum_kernel<<<(FF + 255) / 256, 256>>>(Ws, bb, Wsum, bsum);
        wtrans_split<<<wgrid, wblock>>>(Ws + 1 * FF, Wth[0], Wtl[0]);  // disease self
        wtrans_split<<<wgrid, wblock>>>(Wn + 1 * FF, Wth[1], Wtl[1]);  // disease neigh
        wtrans_split<<<wgrid, wblock>>>(Wsum,        Wth[2], Wtl[2]);  // protein self (folded)
        wtrans_split<<<wgrid, wblock>>>(Wn + 0 * FF, Wth[3], Wtl[3]);
        wtrans_split<<<wgrid, wblock>>>(Wn + 2 * FF, Wth[4], Wtl[4]);
        wtrans_split<<<wgrid, wblock>>>(Wn + 3 * FF, Wth[5], Wtl[5]);

        // ---- disease: Da = Xd@Ws1t + mean_r1(Xp)@Wn1t + b[1]
        seg_mean_split<<<NN, 128>>>(gInP, off + 1 * (NN + 1), val + 1 * EE, Mh[1], Ml[1]);
        {
            GemmArgs a{};
            a.P = 0;
            add_term(a, Xdh, Xdl, Wth[0], Wtl[0]);
            add_term(a, Mh[1], Ml[1], Wth[1], Wtl[1]);
            a.M = ND; a.bias = bb + FH; a.C = Da;
            gemm_mma_kernel<<<ggrid, 256>>>(a);
        }
        // ---- protein: Pa = Xp@Wsumt + mean_r0(Xd)@Wn0t + mean_r2(Xp)@Wn2t + mean_r3(Xp)@Wn3t + bsum
        seg_mean_split<<<NN, 128>>>(gInD, off + 0 * (NN + 1), val + 0 * EE, Mh[0], Ml[0]);
        seg_mean_split<<<NN, 128>>>(gInP, off + 2 * (NN + 1), val + 2 * EE, Mh[2], Ml[2]);
        seg_mean_split<<<NN, 128>>>(gInP, off + 3 * (NN + 1), val + 3 * EE, Mh[3], Ml[3]);
        {
            GemmArgs a{};
            a.P = 0;
            add_term(a, Xph, Xpl, Wth[2], Wtl[2]);
            add_term(a, Mh[0], Ml[0], Wth[3], Wtl[3]);
            add_term(a, Mh[2], Ml[2], Wth[4], Wtl[4]);
            add_term(a, Mh[3], Ml[3], Wth[5], Wtl[5]);
            a.M = NP; a.bias = bsum; a.C = Pa;
            gemm_mma_kernel<<<ggrid, 256>>>(a);
        }

        // ---- BN + ReLU (disease) -> Xd fp32 + Xdh/Xdl
        cudaMemsetAsync(sum, 0, FH * sizeof(float), 0);
        cudaMemsetAsync(sq, 0, FH * sizeof(float), 0);
        colstats_kernel<<<160, FH>>>(Da, ND, sum, sq);
        bn_finalize_kernel<<<1, FH>>>(sum, sq, bng + (li * 2 + 0) * FH, bnb + (li * 2 + 0) * FH,
                                      ND, scale, shift);
        bnrelu_split<<<(ND * FH / 4 + 255) / 256, 256>>>(Da, Xd, Xdh, Xdl, ND, scale, shift);

        // ---- BN + ReLU (protein) -> Xp fp32 + Xph/Xpl
        cudaMemsetAsync(sum, 0, FH * sizeof(float), 0);
        cudaMemsetAsync(sq, 0, FH * sizeof(float), 0);
        colstats_kernel<<<160, FH>>>(Pa, NP, sum, sq);
        bn_finalize_kernel<<<1, FH>>>(sum, sq, bng + (li * 2 + 1) * FH, bnb + (li * 2 + 1) * FH,
                                      NP, scale, shift);
        bnrelu_split<<<(NP * FH / 4 + 255) / 256, 256>>>(Pa, Xp, Xph, Xpl, NP, scale, shift);

        gInD = Xd;
        gInP = Xp;
    }

    // ---- final projections straight into d_out
    wtrans_split<<<wgrid, wblock>>>(pWd, Wth[0], Wtl[0]);
    wtrans_split<<<wgrid, wblock>>>(pWp, Wth[1], Wtl[1]);
    {
        GemmArgs a{};
        a.P = 0;
        add_term(a, Xdh, Xdl, Wth[0], Wtl[0]);
        a.M = ND; a.bias = pbd; a.C = out;
        gemm_mma_kernel<<<ggrid, 256>>>(a);
    }
    {
        GemmArgs a{};
        a.P = 0;
        add_term(a, Xph, Xpl, Wth[1], Wtl[1]);
        a.M = NP; a.bias = pbp; a.C = out + (size_t)ND * FH;
        gemm_mma_kernel<<<ggrid, 256>>>(a);
    }
}

// round 10
// speedup vs baseline: 2.6332x; 1.3192x over previous
#include <cuda_runtime.h>
#include <cuda_fp16.h>
#include <cstdint>

#define ND 20000
#define NP 20000
#define NN 20000
#define FH 512
#define FF (FH * FH)
#define EE 320000

// ---------------- device scratch (static, no allocation) ----------------
__device__ float g_Da[ND * FH], g_Pa[NP * FH];
__device__ __align__(16) __half g_Xdh[ND * FH];
__device__ __align__(16) __half g_Xph[NP * FH];
__device__ __align__(16) __half g_Mh[4][NN * FH];
__device__ __align__(16) __half g_Wth[6][FF];
__device__ float g_Wsum[FF], g_bsum[FH], g_sum[FH], g_sq[FH], g_scale[FH], g_shift[FH];
__device__ int g_off[4 * (NN + 1)], g_cur[4 * (NN + 1)], g_val[4 * EE];

// ---------------- helpers ----------------
__device__ __forceinline__ uint32_t smem_u32(const void* p) {
    uint32_t a;
    asm("{ .reg .u64 t; cvta.to.shared.u64 t, %1; cvt.u32.u64 %0, t; }" : "=r"(a) : "l"(p));
    return a;
}

#define LDSM4(r, addr) \
    asm volatile("ldmatrix.sync.aligned.m8n8.x4.shared.b16 {%0,%1,%2,%3}, [%4];" \
                 : "=r"((r)[0]), "=r"((r)[1]), "=r"((r)[2]), "=r"((r)[3]) : "r"(addr))

#define MMA16816(c, a, b0, b1) \
    asm volatile("mma.sync.aligned.m16n8k16.row.col.f32.f16.f16.f32 " \
                 "{%0,%1,%2,%3}, {%4,%5,%6,%7}, {%8,%9}, {%0,%1,%2,%3};" \
                 : "+f"((c)[0]), "+f"((c)[1]), "+f"((c)[2]), "+f"((c)[3]) \
                 : "r"((a)[0]), "r"((a)[1]), "r"((a)[2]), "r"((a)[3]), "r"(b0), "r"(b1))

#define CP_ASYNC16(dst, src, sz) \
    asm volatile("cp.async.cg.shared.global [%0], [%1], 16, %2;" :: "r"(dst), "l"(src), "r"(sz) : "memory")
#define CP_COMMIT() asm volatile("cp.async.commit_group;" ::: "memory")
#define CP_WAIT1() asm volatile("cp.async.wait_group 1;" ::: "memory")

// ---------------- CSR build ----------------
__global__ void hist_kernel(const int* __restrict__ grp, int* __restrict__ off, int E) {
    int e = blockIdx.x * blockDim.x + threadIdx.x;
    if (e < E) atomicAdd(&off[grp[e] + 1], 1);
}
__global__ void scan_kernel(int* __restrict__ off, int n) {
    __shared__ int ssum[1024];
    const int T = 1024;
    int t = threadIdx.x;
    int chunk = (n + T - 1) / T;
    int lo = 1 + t * chunk;
    int hi = lo + chunk;
    if (hi > n + 1) hi = n + 1;
    int s = 0;
    for (int i = lo; i < hi && i <= n; i++) s += off[i];
    ssum[t] = s;
    __syncthreads();
    for (int d = 1; d < T; d <<= 1) {
        int v = (t >= d) ? ssum[t - d] : 0;
        __syncthreads();
        ssum[t] += v;
        __syncthreads();
    }
    int run = (t > 0) ? ssum[t - 1] : 0;
    for (int i = lo; i < hi && i <= n; i++) {
        run += off[i];
        off[i] = run;
    }
}
__global__ void fill_kernel(const int* __restrict__ grp, const int* __restrict__ oth,
                            int* __restrict__ cur, int* __restrict__ val, int E) {
    int e = blockIdx.x * blockDim.x + threadIdx.x;
    if (e < E) {
        int p = atomicAdd(&cur[grp[e]], 1);
        val[p] = oth[e];
    }
}

// ---------------- segment mean over fp16 rows -> fp16 ----------------
__global__ void seg_mean_h(const __half* __restrict__ X, const int* __restrict__ off,
                           const int* __restrict__ val, __half* __restrict__ out) {
    int d = blockIdx.x;
    int s = off[d], e = off[d + 1];
    int c = threadIdx.x * 4;  // 128 threads * 4 halves
    float a0 = 0.f, a1 = 0.f, a2 = 0.f, a3 = 0.f;
    for (int j = s; j < e; j++) {
        int nb = __ldg(&val[j]);
        uint2 v = *(const uint2*)(X + (size_t)nb * FH + c);
        float2 f0 = __half22float2(*(const __half2*)&v.x);
        float2 f1 = __half22float2(*(const __half2*)&v.y);
        a0 += f0.x; a1 += f0.y; a2 += f1.x; a3 += f1.y;
    }
    int deg = e - s;
    float inv = 1.0f / (float)(deg > 0 ? deg : 1);
    __half2 o0 = __floats2half2_rn(a0 * inv, a1 * inv);
    __half2 o1 = __floats2half2_rn(a2 * inv, a3 * inv);
    uint2 ov;
    ov.x = *(const uint32_t*)&o0;
    ov.y = *(const uint32_t*)&o1;
    *(uint2*)(out + (size_t)d * FH + c) = ov;
}

// ---------------- fp32 -> fp16 ----------------
__global__ void cvt_half(const float* __restrict__ X, __half* __restrict__ H, int n4) {
    int i = blockIdx.x * blockDim.x + threadIdx.x;
    if (i >= n4) return;
    float4 x = ((const float4*)X)[i];
    __half2 h0 = __floats2half2_rn(x.x, x.y);
    __half2 h1 = __floats2half2_rn(x.z, x.w);
    uint2 v;
    v.x = *(const uint32_t*)&h0;
    v.y = *(const uint32_t*)&h1;
    ((uint2*)H)[i] = v;
}

// ---------------- weight transpose: W[K,N] -> T[N,K] fp16 ----------------
__global__ void wtrans_half(const float* __restrict__ W, __half* __restrict__ Th) {
    __shared__ float t[32][33];
    int k = blockIdx.y * 32 + threadIdx.y;
    int n = blockIdx.x * 32 + threadIdx.x;
    t[threadIdx.y][threadIdx.x] = W[(size_t)k * FH + n];
    __syncthreads();
    int nn = blockIdx.x * 32 + threadIdx.y;
    int kk = blockIdx.y * 32 + threadIdx.x;
    Th[(size_t)nn * FH + kk] = __float2half_rn(t[threadIdx.x][threadIdx.y]);
}

// ---------------- weight fold ----------------
__global__ void wsum_kernel(const float* __restrict__ Ws, const float* __restrict__ b,
                            float* __restrict__ Wsum, float* __restrict__ bsum) {
    int i = blockIdx.x * blockDim.x + threadIdx.x;
    if (i < FF) Wsum[i] = Ws[i] + Ws[2 * FF + i] + Ws[3 * FF + i];
    if (i < FH) bsum[i] = b[i] + b[2 * FH + i] + b[3 * FH + i];
}

// ---------------- mma.sync fp16 multi-part GEMM ----------------
// C[M,512] = sum_parts A_p[M,512](f16) @ B_p[512,512]^T(f16, stored [N][K]) + bias
// CTA tile 128x128, BK=32, 8 warps (2x4), warp tile 64x32, 3-stage cp.async.
struct GemmArgs {
    const __half* A[4];
    const __half* B[4];
    int P;   // number of parts; effective K = P*512
    int M;
    const float* bias;
    float* C;
};

#define BM 128
#define BN 128
#define BKk 32
#define STAGES 3
#define STAGE_SZ 16384  // A 8KB + B 8KB

__device__ __forceinline__ void gemm_prefetch(const GemmArgs& args, int kt, uint32_t sbase,
                                              int tid, int row0, int col0) {
    int part = kt >> 4, kk = kt & 15;
    int stage = kt % STAGES;
    const __half* aP = args.A[part];
    const __half* bP = args.B[part];
    int k0 = kk * BKk;
    uint32_t sA = sbase + stage * STAGE_SZ;
    uint32_t sB = sA + 8192;
#pragma unroll
    for (int i = 0; i < 2; i++) {
        int idx = tid + i * 256;
        int r = idx >> 2, ch = idx & 3;
        const __half* g = aP + (size_t)(row0 + r) * FH + k0 + ch * 8;
        uint32_t d = sA + r * 64 + ((ch ^ ((r >> 1) & 3)) << 4);
        int sz = (row0 + r < args.M) ? 16 : 0;
        CP_ASYNC16(d, g, sz);
    }
#pragma unroll
    for (int i = 0; i < 2; i++) {
        int idx = tid + i * 256;
        int r = idx >> 2, ch = idx & 3;
        const __half* g = bP + (size_t)(col0 + r) * FH + k0 + ch * 8;
        uint32_t d = sB + r * 64 + ((ch ^ ((r >> 1) & 3)) << 4);
        CP_ASYNC16(d, g, 16);
    }
    CP_COMMIT();
}

__global__ void __launch_bounds__(256) gemm_mma_kernel(GemmArgs args) {
    __shared__ __align__(128) char smem[STAGES * STAGE_SZ];
    uint32_t sbase = smem_u32(smem);
    int tid = threadIdx.x;
    int w = tid >> 5, lane = tid & 31;
    int wm = w >> 2, wn = w & 3;
    int row0 = blockIdx.x * BM, col0 = blockIdx.y * BN;

    float c[4][4][4];
#pragma unroll
    for (int mi = 0; mi < 4; mi++)
#pragma unroll
        for (int ni = 0; ni < 4; ni++)
#pragma unroll
            for (int q = 0; q < 4; q++) c[mi][ni][q] = 0.f;

    const int T = args.P * 16;
    gemm_prefetch(args, 0, sbase, tid, row0, col0);
    gemm_prefetch(args, 1, sbase, tid, row0, col0);

    for (int kt = 0; kt < T; kt++) {
        CP_WAIT1();
        __syncthreads();
        if (kt + 2 < T)
            gemm_prefetch(args, kt + 2, sbase, tid, row0, col0);
        else
            CP_COMMIT();

        int stage = kt % STAGES;
        uint32_t sA = sbase + stage * STAGE_SZ;
        uint32_t sB = sA + 8192;
#pragma unroll
        for (int ks = 0; ks < 2; ks++) {
            int kc0 = ks * 2;
            uint32_t a[4][4];
#pragma unroll
            for (int mi = 0; mi < 4; mi++) {
                int r = wm * 64 + mi * 16 + (lane & 15);
                int ch = kc0 + (lane >> 4);
                uint32_t addr = sA + r * 64 + ((ch ^ ((r >> 1) & 3)) << 4);
                LDSM4(a[mi], addr);
            }
            uint32_t b[2][4];
#pragma unroll
            for (int nb = 0; nb < 2; nb++) {
                int r = wn * 32 + nb * 16 + ((lane >> 3) & 1) * 8 + (lane & 7);
                int ch = kc0 + (lane >> 4);
                uint32_t addr = sB + r * 64 + ((ch ^ ((r >> 1) & 3)) << 4);
                LDSM4(b[nb], addr);
            }
#pragma unroll
            for (int mi = 0; mi < 4; mi++)
#pragma unroll
                for (int ni = 0; ni < 4; ni++) {
                    uint32_t b0 = b[ni >> 1][ni & 1];
                    uint32_t b1 = b[ni >> 1][2 + (ni & 1)];
                    MMA16816(c[mi][ni], a[mi], b0, b1);
                }
        }
    }

    // epilogue: bias + store
    int gr = lane >> 2, gc = (lane & 3) * 2;
#pragma unroll
    for (int mi = 0; mi < 4; mi++) {
        int r0 = row0 + wm * 64 + mi * 16 + gr;
#pragma unroll
        for (int ni = 0; ni < 4; ni++) {
            int cc = col0 + wn * 32 + ni * 8 + gc;
            float2 bv = *(const float2*)(args.bias + cc);
            if (r0 < args.M) {
                float2 v = make_float2(c[mi][ni][0] + bv.x, c[mi][ni][1] + bv.y);
                *(float2*)(args.C + (size_t)r0 * FH + cc) = v;
            }
            if (r0 + 8 < args.M) {
                float2 v = make_float2(c[mi][ni][2] + bv.x, c[mi][ni][3] + bv.y);
                *(float2*)(args.C + (size_t)(r0 + 8) * FH + cc) = v;
            }
        }
    }
}

// ---------------- BN ----------------
__global__ void colstats_kernel(const float* __restrict__ X, int M,
                                float* __restrict__ sum, float* __restrict__ sq) {
    int c = threadIdx.x;
    float s = 0.f, s2 = 0.f;
    for (int r = blockIdx.x; r < M; r += gridDim.x) {
        float v = X[(size_t)r * FH + c];
        s += v;
        s2 += v * v;
    }
    atomicAdd(&sum[c], s);
    atomicAdd(&sq[c], s2);
}
__global__ void bn_finalize_kernel(const float* __restrict__ sum, const float* __restrict__ sq,
                                   const float* __restrict__ gamma, const float* __restrict__ beta,
                                   int M, float* __restrict__ scale, float* __restrict__ shift) {
    int c = threadIdx.x;
    float m = sum[c] / (float)M;
    float var = sq[c] / (float)M - m * m;
    float rstd = rsqrtf(var + 1e-5f);
    float sc = gamma[c] * rstd;
    scale[c] = sc;
    shift[c] = beta[c] - m * sc;
}
// BN+ReLU -> fp16 activations
__global__ void bnrelu_half(const float* __restrict__ Xin, __half* __restrict__ H, int M,
                            const float* __restrict__ scale, const float* __restrict__ shift) {
    int i = blockIdx.x * blockDim.x + threadIdx.x;
    int total = M * FH / 4;
    if (i >= total) return;
    int c = (i & 127) * 4;
    float4 x = ((const float4*)Xin)[i];
    float4 sc = *(const float4*)(scale + c);
    float4 sh = *(const float4*)(shift + c);
    float y0 = fmaxf(fmaf(x.x, sc.x, sh.x), 0.f);
    float y1 = fmaxf(fmaf(x.y, sc.y, sh.y), 0.f);
    float y2 = fmaxf(fmaf(x.z, sc.z, sh.z), 0.f);
    float y3 = fmaxf(fmaf(x.w, sc.w, sh.w), 0.f);
    __half2 h0 = __floats2half2_rn(y0, y1);
    __half2 h1 = __floats2half2_rn(y2, y3);
    uint2 v;
    v.x = *(const uint32_t*)&h0;
    v.y = *(const uint32_t*)&h1;
    ((uint2*)H)[i] = v;
}

// ---------------- host orchestration ----------------
extern "C" void kernel_launch(void* const* d_in, const int* in_sizes, int n_in,
                              void* d_out, int out_size) {
    const float* h_d = (const float*)d_in[0];
    const float* h_p = (const float*)d_in[1];
    const float* Ws1 = (const float*)d_in[2];
    const float* Wn1 = (const float*)d_in[3];
    const float* b1  = (const float*)d_in[4];
    const float* Ws2 = (const float*)d_in[5];
    const float* Wn2 = (const float*)d_in[6];
    const float* b2  = (const float*)d_in[7];
    const float* bng = (const float*)d_in[8];
    const float* bnb = (const float*)d_in[9];
    const float* pWd = (const float*)d_in[10];
    const float* pbd = (const float*)d_in[11];
    const float* pWp = (const float*)d_in[12];
    const float* pbp = (const float*)d_in[13];
    const int* a_src = (const int*)d_in[14];
    const int* a_dst = (const int*)d_in[15];
    const int* i_src = (const int*)d_in[16];
    const int* i_dst = (const int*)d_in[17];
    float* out = (float*)d_out;

    float *Da, *Pa, *Wsum, *bsum, *sum, *sq, *scale, *shift;
    __half *Xdh, *Xph, *MhB, *WthB;
    int *off, *cur, *val;
    cudaGetSymbolAddress((void**)&Da, g_Da);
    cudaGetSymbolAddress((void**)&Pa, g_Pa);
    cudaGetSymbolAddress((void**)&Wsum, g_Wsum);
    cudaGetSymbolAddress((void**)&bsum, g_bsum);
    cudaGetSymbolAddress((void**)&sum, g_sum);
    cudaGetSymbolAddress((void**)&sq, g_sq);
    cudaGetSymbolAddress((void**)&scale, g_scale);
    cudaGetSymbolAddress((void**)&shift, g_shift);
    cudaGetSymbolAddress((void**)&Xdh, g_Xdh);
    cudaGetSymbolAddress((void**)&Xph, g_Xph);
    cudaGetSymbolAddress((void**)&MhB, g_Mh);
    cudaGetSymbolAddress((void**)&WthB, g_Wth);
    cudaGetSymbolAddress((void**)&off, g_off);
    cudaGetSymbolAddress((void**)&cur, g_cur);
    cudaGetSymbolAddress((void**)&val, g_val);

    __half *Mh[4], *Wth[6];
    for (int i = 0; i < 4; i++) Mh[i] = MhB + (size_t)i * NN * FH;
    for (int i = 0; i < 6; i++) Wth[i] = WthB + (size_t)i * FF;

    // ---- CSR build: 0:(a_dst<-a_src) 1:(a_src<-a_dst) 2:(i_dst<-i_src) 3:(i_src<-i_dst)
    const int* grps[4] = {a_dst, a_src, i_dst, i_src};
    const int* oths[4] = {a_src, a_dst, i_src, i_dst};
    for (int r = 0; r < 4; r++) {
        int* offr = off + r * (NN + 1);
        int* curr = cur + r * (NN + 1);
        int* valr = val + r * EE;
        cudaMemsetAsync(offr, 0, (NN + 1) * sizeof(int), 0);
        hist_kernel<<<(EE + 255) / 256, 256>>>(grps[r], offr, EE);
        scan_kernel<<<1, 1024>>>(offr, NN);
        cudaMemcpyAsync(curr, offr, (NN + 1) * sizeof(int), cudaMemcpyDeviceToDevice, 0);
        fill_kernel<<<(EE + 255) / 256, 256>>>(grps[r], oths[r], curr, valr, EE);
    }

    // ---- initial activation conversion to fp16
    cvt_half<<<(ND * FH / 4 + 255) / 256, 256>>>(h_d, Xdh, ND * FH / 4);
    cvt_half<<<(NP * FH / 4 + 255) / 256, 256>>>(h_p, Xph, NP * FH / 4);

    dim3 wgrid(16, 16), wblock(32, 32);
    dim3 ggrid((ND + BM - 1) / BM, FH / BN);

    for (int li = 0; li < 2; li++) {
        const float* Ws = li ? Ws2 : Ws1;
        const float* Wn = li ? Wn2 : Wn1;
        const float* bb = li ? b2 : b1;

        wsum_kernel<<<(FF + 255) / 256, 256>>>(Ws, bb, Wsum, bsum);
        wtrans_half<<<wgrid, wblock>>>(Ws + 1 * FF, Wth[0]);  // disease self
        wtrans_half<<<wgrid, wblock>>>(Wn + 1 * FF, Wth[1]);  // disease neigh
        wtrans_half<<<wgrid, wblock>>>(Wsum,        Wth[2]);  // protein self (folded)
        wtrans_half<<<wgrid, wblock>>>(Wn + 0 * FF, Wth[3]);
        wtrans_half<<<wgrid, wblock>>>(Wn + 2 * FF, Wth[4]);
        wtrans_half<<<wgrid, wblock>>>(Wn + 3 * FF, Wth[5]);

        // ---- disease: Da = Xd@Ws1t + mean_r1(Xp)@Wn1t + b[1]
        seg_mean_h<<<NN, 128>>>(Xph, off + 1 * (NN + 1), val + 1 * EE, Mh[1]);
        {
            GemmArgs a{};
            a.A[0] = Xdh;   a.B[0] = Wth[0];
            a.A[1] = Mh[1]; a.B[1] = Wth[1];
            a.P = 2; a.M = ND; a.bias = bb + FH; a.C = Da;
            gemm_mma_kernel<<<ggrid, 256>>>(a);
        }
        // ---- protein: Pa = Xp@Wsumt + mean_r0(Xd)@Wn0t + mean_r2(Xp)@Wn2t + mean_r3(Xp)@Wn3t + bsum
        seg_mean_h<<<NN, 128>>>(Xdh, off + 0 * (NN + 1), val + 0 * EE, Mh[0]);
        seg_mean_h<<<NN, 128>>>(Xph, off + 2 * (NN + 1), val + 2 * EE, Mh[2]);
        seg_mean_h<<<NN, 128>>>(Xph, off + 3 * (NN + 1), val + 3 * EE, Mh[3]);
        {
            GemmArgs a{};
            a.A[0] = Xph;   a.B[0] = Wth[2];
            a.A[1] = Mh[0]; a.B[1] = Wth[3];
            a.A[2] = Mh[2]; a.B[2] = Wth[4];
            a.A[3] = Mh[3]; a.B[3] = Wth[5];
            a.P = 4; a.M = NP; a.bias = bsum; a.C = Pa;
            gemm_mma_kernel<<<ggrid, 256>>>(a);
        }

        // ---- BN + ReLU (disease) -> Xdh fp16
        cudaMemsetAsync(sum, 0, FH * sizeof(float), 0);
        cudaMemsetAsync(sq, 0, FH * sizeof(float), 0);
        colstats_kernel<<<160, FH>>>(Da, ND, sum, sq);
        bn_finalize_kernel<<<1, FH>>>(sum, sq, bng + (li * 2 + 0) * FH, bnb + (li * 2 + 0) * FH,
                                      ND, scale, shift);
        bnrelu_half<<<(ND * FH / 4 + 255) / 256, 256>>>(Da, Xdh, ND, scale, shift);

        // ---- BN + ReLU (protein) -> Xph fp16
        cudaMemsetAsync(sum, 0, FH * sizeof(float), 0);
        cudaMemsetAsync(sq, 0, FH * sizeof(float), 0);
        colstats_kernel<<<160, FH>>>(Pa, NP, sum, sq);
        bn_finalize_kernel<<<1, FH>>>(sum, sq, bng + (li * 2 + 1) * FH, bnb + (li * 2 + 1) * FH,
                                      NP, scale, shift);
        bnrelu_half<<<(NP * FH / 4 + 255) / 256, 256>>>(Pa, Xph, NP, scale, shift);
    }

    // ---- final projections straight into d_out
    wtrans_half<<<wgrid, wblock>>>(pWd, Wth[0]);
    wtrans_half<<<wgrid, wblock>>>(pWp, Wth[1]);
    {
        GemmArgs a{};
        a.A[0] = Xdh; a.B[0] = Wth[0];
        a.P = 1; a.M = ND; a.bias = pbd; a.C = out;
        gemm_mma_kernel<<<ggrid, 256>>>(a);
    }
    {
        GemmArgs a{};
        a.A[0] = Xph; a.B[0] = Wth[1];
        a.P = 1; a.M = NP; a.bias = pbp; a.C = out + (size_t)ND * FH;
        gemm_mma_kernel<<<ggrid, 256>>>(a);
    }
}

// round 12
// speedup vs baseline: 4.6267x; 1.7571x over previous
#include <cuda_runtime.h>
#include <cuda_fp16.h>
#include <cstdint>

#define ND 20000
#define NP 20000
#define NN 20000
#define FH 512
#define FF (FH * FH)
#define EE 320000
#define CS_BLKS 160

// ---------------- device scratch (static, no allocation) ----------------
__device__ float g_Da[ND * FH], g_Pa[NP * FH];
__device__ __align__(16) __half g_Xdh[ND * FH];
__device__ __align__(16) __half g_Xph[NP * FH];
__device__ __align__(16) __half g_Mh[4][NN * FH];
__device__ __align__(16) __half g_Wth[6][FF];
__device__ float g_bsum[FH], g_scale[FH], g_shift[FH];
__device__ float g_psum[CS_BLKS * FH], g_psq[CS_BLKS * FH];
__device__ int g_off[4 * (NN + 1)], g_cur[4 * (NN + 1)], g_val[4 * EE];

// ---------------- helpers ----------------
__device__ __forceinline__ uint32_t smem_u32(const void* p) {
    uint32_t a;
    asm("{ .reg .u64 t; cvta.to.shared.u64 t, %1; cvt.u32.u64 %0, t; }" : "=r"(a) : "l"(p));
    return a;
}

#define LDSM4(r, addr) \
    asm volatile("ldmatrix.sync.aligned.m8n8.x4.shared.b16 {%0,%1,%2,%3}, [%4];" \
                 : "=r"((r)[0]), "=r"((r)[1]), "=r"((r)[2]), "=r"((r)[3]) : "r"(addr))

#define MMA16816(c, a, b0, b1) \
    asm volatile("mma.sync.aligned.m16n8k16.row.col.f32.f16.f16.f32 " \
                 "{%0,%1,%2,%3}, {%4,%5,%6,%7}, {%8,%9}, {%0,%1,%2,%3};" \
                 : "+f"((c)[0]), "+f"((c)[1]), "+f"((c)[2]), "+f"((c)[3]) \
                 : "r"((a)[0]), "r"((a)[1]), "r"((a)[2]), "r"((a)[3]), "r"(b0), "r"(b1))

#define CP_ASYNC16(dst, src, sz) \
    asm volatile("cp.async.cg.shared.global [%0], [%1], 16, %2;" :: "r"(dst), "l"(src), "r"(sz) : "memory")
#define CP_COMMIT() asm volatile("cp.async.commit_group;" ::: "memory")
#define CP_WAIT1() asm volatile("cp.async.wait_group 1;" ::: "memory")

// ---------------- CSR build ----------------
__global__ void hist_kernel(const int* __restrict__ grp, int* __restrict__ off, int E) {
    int e = blockIdx.x * blockDim.x + threadIdx.x;
    if (e < E) atomicAdd(&off[grp[e] + 1], 1);
}
__global__ void scan_kernel(int* __restrict__ off, int n) {
    __shared__ int ssum[1024];
    const int T = 1024;
    int t = threadIdx.x;
    int chunk = (n + T - 1) / T;
    int lo = 1 + t * chunk;
    int hi = lo + chunk;
    if (hi > n + 1) hi = n + 1;
    int s = 0;
    for (int i = lo; i < hi && i <= n; i++) s += off[i];
    ssum[t] = s;
    __syncthreads();
    for (int d = 1; d < T; d <<= 1) {
        int v = (t >= d) ? ssum[t - d] : 0;
        __syncthreads();
        ssum[t] += v;
        __syncthreads();
    }
    int run = (t > 0) ? ssum[t - 1] : 0;
    for (int i = lo; i < hi && i <= n; i++) {
        run += off[i];
        off[i] = run;
    }
}
__global__ void fill_kernel(const int* __restrict__ grp, const int* __restrict__ oth,
                            int* __restrict__ cur, int* __restrict__ val, int E) {
    int e = blockIdx.x * blockDim.x + threadIdx.x;
    if (e < E) {
        int p = atomicAdd(&cur[grp[e]], 1);
        val[p] = oth[e];
    }
}

// ---------------- fused 4-relation segment mean (fp16, MLP-unrolled) ----------------
struct SegArgs {
    const __half* X[4];
    const int* off[4];
    const int* val[4];
    __half* out[4];
};
__global__ void seg_mean4(SegArgs args) {
    int rel = blockIdx.y;
    const __half* X = args.X[rel];
    const int* off = args.off[rel];
    const int* val = args.val[rel];
    __half* out = args.out[rel];
    int c = threadIdx.x * 4;  // 128 threads * 4 halves = 512
    for (int d = blockIdx.x; d < NN; d += gridDim.x) {
        int s = off[d], e = off[d + 1];
        float a0 = 0.f, a1 = 0.f, a2 = 0.f, a3 = 0.f;
        int j = s;
        for (; j + 4 <= e; j += 4) {
            int n0 = __ldg(&val[j]);
            int n1 = __ldg(&val[j + 1]);
            int n2 = __ldg(&val[j + 2]);
            int n3 = __ldg(&val[j + 3]);
            uint2 v0 = *(const uint2*)(X + (size_t)n0 * FH + c);
            uint2 v1 = *(const uint2*)(X + (size_t)n1 * FH + c);
            uint2 v2 = *(const uint2*)(X + (size_t)n2 * FH + c);
            uint2 v3 = *(const uint2*)(X + (size_t)n3 * FH + c);
            float2 f;
            f = __half22float2(*(const __half2*)&v0.x); a0 += f.x; a1 += f.y;
            f = __half22float2(*(const __half2*)&v0.y); a2 += f.x; a3 += f.y;
            f = __half22float2(*(const __half2*)&v1.x); a0 += f.x; a1 += f.y;
            f = __half22float2(*(const __half2*)&v1.y); a2 += f.x; a3 += f.y;
            f = __half22float2(*(const __half2*)&v2.x); a0 += f.x; a1 += f.y;
            f = __half22float2(*(const __half2*)&v2.y); a2 += f.x; a3 += f.y;
            f = __half22float2(*(const __half2*)&v3.x); a0 += f.x; a1 += f.y;
            f = __half22float2(*(const __half2*)&v3.y); a2 += f.x; a3 += f.y;
        }
        for (; j < e; j++) {
            int nb = __ldg(&val[j]);
            uint2 v = *(const uint2*)(X + (size_t)nb * FH + c);
            float2 f0 = __half22float2(*(const __half2*)&v.x);
            float2 f1 = __half22float2(*(const __half2*)&v.y);
            a0 += f0.x; a1 += f0.y; a2 += f1.x; a3 += f1.y;
        }
        int deg = e - s;
        float inv = 1.0f / (float)(deg > 0 ? deg : 1);
        __half2 o0 = __floats2half2_rn(a0 * inv, a1 * inv);
        __half2 o1 = __floats2half2_rn(a2 * inv, a3 * inv);
        uint2 ov;
        ov.x = *(const uint32_t*)&o0;
        ov.y = *(const uint32_t*)&o1;
        *(uint2*)(out + (size_t)d * FH + c) = ov;
    }
}

// ---------------- fp32 -> fp16 ----------------
__global__ void cvt_half(const float* __restrict__ X, __half* __restrict__ H, int n4) {
    int i = blockIdx.x * blockDim.x + threadIdx.x;
    if (i >= n4) return;
    float4 x = ((const float4*)X)[i];
    __half2 h0 = __floats2half2_rn(x.x, x.y);
    __half2 h1 = __floats2half2_rn(x.z, x.w);
    uint2 v;
    v.x = *(const uint32_t*)&h0;
    v.y = *(const uint32_t*)&h1;
    ((uint2*)H)[i] = v;
}

// ---------------- fused 6-way weight transpose (+fold for z=2): W[K,N] -> T[N,K] fp16 ----
__global__ void wtrans6(const float* __restrict__ Ws, const float* __restrict__ Wn,
                        __half* __restrict__ dstB) {
    __shared__ float t[32][33];
    int z = blockIdx.z;
    int k = blockIdx.y * 32 + threadIdx.y;
    int n = blockIdx.x * 32 + threadIdx.x;
    size_t idx = (size_t)k * FH + n;
    float v;
    switch (z) {
        case 0: v = Ws[FF + idx]; break;
        case 1: v = Wn[FF + idx]; break;
        case 2: v = Ws[idx] + Ws[2 * FF + idx] + Ws[3 * FF + idx]; break;
        case 3: v = Wn[idx]; break;
        case 4: v = Wn[2 * FF + idx]; break;
        default: v = Wn[3 * FF + idx]; break;
    }
    t[threadIdx.y][threadIdx.x] = v;
    __syncthreads();
    int nn = blockIdx.x * 32 + threadIdx.y;
    int kk = blockIdx.y * 32 + threadIdx.x;
    dstB[(size_t)z * FF + (size_t)nn * FH + kk] = __float2half_rn(t[threadIdx.x][threadIdx.y]);
}
__global__ void wtrans_half(const float* __restrict__ W, __half* __restrict__ Th) {
    __shared__ float t[32][33];
    int k = blockIdx.y * 32 + threadIdx.y;
    int n = blockIdx.x * 32 + threadIdx.x;
    t[threadIdx.y][threadIdx.x] = W[(size_t)k * FH + n];
    __syncthreads();
    int nn = blockIdx.x * 32 + threadIdx.y;
    int kk = blockIdx.y * 32 + threadIdx.x;
    Th[(size_t)nn * FH + kk] = __float2half_rn(t[threadIdx.x][threadIdx.y]);
}
__global__ void bsum_kernel(const float* __restrict__ b, float* __restrict__ bsum) {
    int c = threadIdx.x;
    bsum[c] = b[c] + b[2 * FH + c] + b[3 * FH + c];
}

// ---------------- mma.sync fp16 multi-part GEMM (BK=64, 3-stage, 96KB dyn smem) ------
// C[M,512] = sum_parts A_p[M,512](f16) @ B_p[512,512]^T(f16, stored [N][K]) + bias
struct GemmArgs {
    const __half* A[4];
    const __half* B[4];
    int P;   // parts; effective K = P*512
    int M;
    const float* bias;
    float* C;
};

#define BM 128
#define BN 128
#define BK 64
#define STAGES 3
#define STAGE_SZ 32768  // A 16KB + B 16KB
#define GEMM_SMEM (STAGES * STAGE_SZ)

__device__ __forceinline__ void gemm_prefetch(const GemmArgs& args, int kt, uint32_t sbase,
                                              int tid, int row0, int col0) {
    int part = kt >> 3, kk = kt & 7;
    int stage = kt % STAGES;
    const __half* aP = args.A[part];
    const __half* bP = args.B[part];
    int k0 = kk * BK;
    uint32_t sA = sbase + stage * STAGE_SZ;
    uint32_t sB = sA + 16384;
#pragma unroll
    for (int i = 0; i < 4; i++) {
        int idx = tid + i * 256;  // 0..1023
        int r = idx >> 3, ch = idx & 7;
        const __half* g = aP + (size_t)(row0 + r) * FH + k0 + ch * 8;
        uint32_t d = sA + r * 128 + ((ch ^ (r & 7)) << 4);
        int sz = (row0 + r < args.M) ? 16 : 0;
        CP_ASYNC16(d, g, sz);
    }
#pragma unroll
    for (int i = 0; i < 4; i++) {
        int idx = tid + i * 256;
        int r = idx >> 3, ch = idx & 7;
        const __half* g = bP + (size_t)(col0 + r) * FH + k0 + ch * 8;
        uint32_t d = sB + r * 128 + ((ch ^ (r & 7)) << 4);
        CP_ASYNC16(d, g, 16);
    }
    CP_COMMIT();
}

__global__ void __launch_bounds__(256) gemm_mma_kernel(GemmArgs args) {
    extern __shared__ __align__(128) char smem[];
    uint32_t sbase = smem_u32(smem);
    int tid = threadIdx.x;
    int w = tid >> 5, lane = tid & 31;
    int wm = w >> 2, wn = w & 3;
    int row0 = blockIdx.x * BM, col0 = blockIdx.y * BN;

    float c[4][4][4];
#pragma unroll
    for (int mi = 0; mi < 4; mi++)
#pragma unroll
        for (int ni = 0; ni < 4; ni++)
#pragma unroll
            for (int q = 0; q < 4; q++) c[mi][ni][q] = 0.f;

    const int T = args.P * 8;
    gemm_prefetch(args, 0, sbase, tid, row0, col0);
    gemm_prefetch(args, 1, sbase, tid, row0, col0);

    for (int kt = 0; kt < T; kt++) {
        CP_WAIT1();
        __syncthreads();
        if (kt + 2 < T)
            gemm_prefetch(args, kt + 2, sbase, tid, row0, col0);
        else
            CP_COMMIT();

        int stage = kt % STAGES;
        uint32_t sA = sbase + stage * STAGE_SZ;
        uint32_t sB = sA + 16384;
#pragma unroll
        for (int ks = 0; ks < 4; ks++) {
            int kc0 = ks * 2;
            uint32_t a[4][4];
#pragma unroll
            for (int mi = 0; mi < 4; mi++) {
                int r = wm * 64 + mi * 16 + (lane & 15);
                int ch = kc0 + (lane >> 4);
                uint32_t addr = sA + r * 128 + ((ch ^ (r & 7)) << 4);
                LDSM4(a[mi], addr);
            }
            uint32_t b[2][4];
#pragma unroll
            for (int nb = 0; nb < 2; nb++) {
                int r = wn * 32 + nb * 16 + ((lane >> 3) & 1) * 8 + (lane & 7);
                int ch = kc0 + (lane >> 4);
                uint32_t addr = sB + r * 128 + ((ch ^ (r & 7)) << 4);
                LDSM4(b[nb], addr);
            }
#pragma unroll
            for (int mi = 0; mi < 4; mi++)
#pragma unroll
                for (int ni = 0; ni < 4; ni++) {
                    uint32_t b0 = b[ni >> 1][ni & 1];
                    uint32_t b1 = b[ni >> 1][2 + (ni & 1)];
                    MMA16816(c[mi][ni], a[mi], b0, b1);
                }
        }
    }

    // epilogue: bias + store
    int gr = lane >> 2, gc = (lane & 3) * 2;
#pragma unroll
    for (int mi = 0; mi < 4; mi++) {
        int r0 = row0 + wm * 64 + mi * 16 + gr;
#pragma unroll
        for (int ni = 0; ni < 4; ni++) {
            int cc = col0 + wn * 32 + ni * 8 + gc;
            float2 bv = *(const float2*)(args.bias + cc);
            if (r0 < args.M) {
                float2 v = make_float2(c[mi][ni][0] + bv.x, c[mi][ni][1] + bv.y);
                *(float2*)(args.C + (size_t)r0 * FH + cc) = v;
            }
            if (r0 + 8 < args.M) {
                float2 v = make_float2(c[mi][ni][2] + bv.x, c[mi][ni][3] + bv.y);
                *(float2*)(args.C + (size_t)(r0 + 8) * FH + cc) = v;
            }
        }
    }
}

// ---------------- BN (atomic-free two-phase stats) ----------------
__global__ void colstats2(const float* __restrict__ X, int M,
                          float* __restrict__ psum, float* __restrict__ psq) {
    int c = threadIdx.x;  // 512
    int b = blockIdx.x;   // CS_BLKS
    float s = 0.f, s2 = 0.f;
    for (int r = b; r < M; r += CS_BLKS) {
        float v = X[(size_t)r * FH + c];
        s += v;
        s2 += v * v;
    }
    psum[b * FH + c] = s;
    psq[b * FH + c] = s2;
}
__global__ void bn_finalize2(const float* __restrict__ psum, const float* __restrict__ psq,
                             const float* __restrict__ gamma, const float* __restrict__ beta,
                             int M, float* __restrict__ scale, float* __restrict__ shift) {
    int c = threadIdx.x;
    float s = 0.f, s2 = 0.f;
    for (int b = 0; b < CS_BLKS; b++) {
        s += psum[b * FH + c];
        s2 += psq[b * FH + c];
    }
    float m = s / (float)M;
    float var = s2 / (float)M - m * m;
    float rstd = rsqrtf(var + 1e-5f);
    float sc = gamma[c] * rstd;
    scale[c] = sc;
    shift[c] = beta[c] - m * sc;
}
__global__ void bnrelu_half(const float* __restrict__ Xin, __half* __restrict__ H, int M,
                            const float* __restrict__ scale, const float* __restrict__ shift) {
    int i = blockIdx.x * blockDim.x + threadIdx.x;
    int total = M * FH / 4;
    if (i >= total) return;
    int c = (i & 127) * 4;
    float4 x = ((const float4*)Xin)[i];
    float4 sc = *(const float4*)(scale + c);
    float4 sh = *(const float4*)(shift + c);
    float y0 = fmaxf(fmaf(x.x, sc.x, sh.x), 0.f);
    float y1 = fmaxf(fmaf(x.y, sc.y, sh.y), 0.f);
    float y2 = fmaxf(fmaf(x.z, sc.z, sh.z), 0.f);
    float y3 = fmaxf(fmaf(x.w, sc.w, sh.w), 0.f);
    __half2 h0 = __floats2half2_rn(y0, y1);
    __half2 h1 = __floats2half2_rn(y2, y3);
    uint2 v;
    v.x = *(const uint32_t*)&h0;
    v.y = *(const uint32_t*)&h1;
    ((uint2*)H)[i] = v;
}

// ---------------- host orchestration ----------------
extern "C" void kernel_launch(void* const* d_in, const int* in_sizes, int n_in,
                              void* d_out, int out_size) {
    const float* h_d = (const float*)d_in[0];
    const float* h_p = (const float*)d_in[1];
    const float* Ws1 = (const float*)d_in[2];
    const float* Wn1 = (const float*)d_in[3];
    const float* b1  = (const float*)d_in[4];
    const float* Ws2 = (const float*)d_in[5];
    const float* Wn2 = (const float*)d_in[6];
    const float* b2  = (const float*)d_in[7];
    const float* bng = (const float*)d_in[8];
    const float* bnb = (const float*)d_in[9];
    const float* pWd = (const float*)d_in[10];
    const float* pbd = (const float*)d_in[11];
    const float* pWp = (const float*)d_in[12];
    const float* pbp = (const float*)d_in[13];
    const int* a_src = (const int*)d_in[14];
    const int* a_dst = (const int*)d_in[15];
    const int* i_src = (const int*)d_in[16];
    const int* i_dst = (const int*)d_in[17];
    float* out = (float*)d_out;

    cudaFuncSetAttribute(gemm_mma_kernel, cudaFuncAttributeMaxDynamicSharedMemorySize,
                         GEMM_SMEM);

    float *Da, *Pa, *bsum, *psum, *psq, *scale, *shift;
    __half *Xdh, *Xph, *MhB, *WthB;
    int *off, *cur, *val;
    cudaGetSymbolAddress((void**)&Da, g_Da);
    cudaGetSymbolAddress((void**)&Pa, g_Pa);
    cudaGetSymbolAddress((void**)&bsum, g_bsum);
    cudaGetSymbolAddress((void**)&psum, g_psum);
    cudaGetSymbolAddress((void**)&psq, g_psq);
    cudaGetSymbolAddress((void**)&scale, g_scale);
    cudaGetSymbolAddress((void**)&shift, g_shift);
    cudaGetSymbolAddress((void**)&Xdh, g_Xdh);
    cudaGetSymbolAddress((void**)&Xph, g_Xph);
    cudaGetSymbolAddress((void**)&MhB, g_Mh);
    cudaGetSymbolAddress((void**)&WthB, g_Wth);
    cudaGetSymbolAddress((void**)&off, g_off);
    cudaGetSymbolAddress((void**)&cur, g_cur);
    cudaGetSymbolAddress((void**)&val, g_val);

    __half *Mh[4], *Wth[6];
    for (int i = 0; i < 4; i++) Mh[i] = MhB + (size_t)i * NN * FH;
    for (int i = 0; i < 6; i++) Wth[i] = WthB + (size_t)i * FF;

    // ---- CSR build: 0:(a_dst<-a_src) 1:(a_src<-a_dst) 2:(i_dst<-i_src) 3:(i_src<-i_dst)
    const int* grps[4] = {a_dst, a_src, i_dst, i_src};
    const int* oths[4] = {a_src, a_dst, i_src, i_dst};
    for (int r = 0; r < 4; r++) {
        int* offr = off + r * (NN + 1);
        int* curr = cur + r * (NN + 1);
        int* valr = val + r * EE;
        cudaMemsetAsync(offr, 0, (NN + 1) * sizeof(int), 0);
        hist_kernel<<<(EE + 255) / 256, 256>>>(grps[r], offr, EE);
        scan_kernel<<<1, 1024>>>(offr, NN);
        cudaMemcpyAsync(curr, offr, (NN + 1) * sizeof(int), cudaMemcpyDeviceToDevice, 0);
        fill_kernel<<<(EE + 255) / 256, 256>>>(grps[r], oths[r], curr, valr, EE);
    }

    // ---- initial activation conversion to fp16
    cvt_half<<<(ND * FH / 4 + 255) / 256, 256>>>(h_d, Xdh, ND * FH / 4);
    cvt_half<<<(NP * FH / 4 + 255) / 256, 256>>>(h_p, Xph, NP * FH / 4);

    dim3 wgrid(16, 16), wblock(32, 32);
    dim3 w6grid(16, 16, 6);
    dim3 ggrid((ND + BM - 1) / BM, FH / BN);
    dim3 sgrid(2048, 4);

    for (int li = 0; li < 2; li++) {
        const float* Ws = li ? Ws2 : Ws1;
        const float* Wn = li ? Wn2 : Wn1;
        const float* bb = li ? b2 : b1;

        wtrans6<<<w6grid, wblock>>>(Ws, Wn, WthB);
        bsum_kernel<<<1, FH>>>(bb, bsum);

        // ---- all 4 segment means in one launch
        {
            SegArgs sa{};
            sa.X[0] = Xdh; sa.off[0] = off + 0 * (NN + 1); sa.val[0] = val + 0 * EE; sa.out[0] = Mh[0];
            sa.X[1] = Xph; sa.off[1] = off + 1 * (NN + 1); sa.val[1] = val + 1 * EE; sa.out[1] = Mh[1];
            sa.X[2] = Xph; sa.off[2] = off + 2 * (NN + 1); sa.val[2] = val + 2 * EE; sa.out[2] = Mh[2];
            sa.X[3] = Xph; sa.off[3] = off + 3 * (NN + 1); sa.val[3] = val + 3 * EE; sa.out[3] = Mh[3];
            seg_mean4<<<sgrid, 128>>>(sa);
        }

        // ---- disease: Da = Xd@Ws1t + mean_r1(Xp)@Wn1t + b[1]
        {
            GemmArgs a{};
            a.A[0] = Xdh;   a.B[0] = Wth[0];
            a.A[1] = Mh[1]; a.B[1] = Wth[1];
            a.P = 2; a.M = ND; a.bias = bb + FH; a.C = Da;
            gemm_mma_kernel<<<ggrid, 256, GEMM_SMEM>>>(a);
        }
        // ---- protein: Pa = Xp@Wsumt + mean_r0(Xd)@Wn0t + mean_r2(Xp)@Wn2t + mean_r3(Xp)@Wn3t + bsum
        {
            GemmArgs a{};
            a.A[0] = Xph;   a.B[0] = Wth[2];
            a.A[1] = Mh[0]; a.B[1] = Wth[3];
            a.A[2] = Mh[2]; a.B[2] = Wth[4];
            a.A[3] = Mh[3]; a.B[3] = Wth[5];
            a.P = 4; a.M = NP; a.bias = bsum; a.C = Pa;
            gemm_mma_kernel<<<ggrid, 256, GEMM_SMEM>>>(a);
        }

        // ---- BN + ReLU (disease) -> Xdh fp16
        colstats2<<<CS_BLKS, FH>>>(Da, ND, psum, psq);
        bn_finalize2<<<1, FH>>>(psum, psq, bng + (li * 2 + 0) * FH, bnb + (li * 2 + 0) * FH,
                                ND, scale, shift);
        bnrelu_half<<<(ND * FH / 4 + 255) / 256, 256>>>(Da, Xdh, ND, scale, shift);

        // ---- BN + ReLU (protein) -> Xph fp16
        colstats2<<<CS_BLKS, FH>>>(Pa, NP, psum, psq);
        bn_finalize2<<<1, FH>>>(psum, psq, bng + (li * 2 + 1) * FH, bnb + (li * 2 + 1) * FH,
                                NP, scale, shift);
        bnrelu_half<<<(NP * FH / 4 + 255) / 256, 256>>>(Pa, Xph, NP, scale, shift);
    }

    // ---- final projections straight into d_out
    wtrans_half<<<wgrid, wblock>>>(pWd, Wth[0]);
    wtrans_half<<<wgrid, wblock>>>(pWp, Wth[1]);
    {
        GemmArgs a{};
        a.A[0] = Xdh; a.B[0] = Wth[0];
        a.P = 1; a.M = ND; a.bias = pbd; a.C = out;
        gemm_mma_kernel<<<ggrid, 256, GEMM_SMEM>>>(a);
    }
    {
        GemmArgs a{};
        a.A[0] = Xph; a.B[0] = Wth[1];
        a.P = 1; a.M = NP; a.bias = pbp; a.C = out + (size_t)ND * FH;
        gemm_mma_kernel<<<ggrid, 256, GEMM_SMEM>>>(a);
    }
}